// round 16
// baseline (speedup 1.0000x reference)
#include <cuda_runtime.h>
#include <cuda_fp16.h>
#include <math.h>
#include <stdint.h>

#define BSZ 4
#define SEQ 2048
#define DIM 1024
#define NH  16
#define DH  64

// ---------------------------------------------------------------------------
// f16 packed layouts (all u32 = __half2):
//  interleaved (hi/lo split operands), per row of C cols: C/16 chunks x 16 u32
//  pairs (single-f16 operands), per row: C/16 chunks x 8 u32
// p layout: [b, h, q, k]
// ---------------------------------------------------------------------------
__device__ uint32_t g_xp  [(size_t)8192*1024];        // X hi/lo interleaved
__device__ uint32_t g_wqp [(size_t)1024*1024];
__device__ uint32_t g_wkp [(size_t)1024*1024];
__device__ uint32_t g_wvp [(size_t)1024*1024];
__device__ uint32_t g_wop [(size_t)1024*512];         // Wo pairs
__device__ uint32_t g_qp  [(size_t)BSZ*NH*SEQ*64];    // q/8 hi/lo, rows=(bh,s)
__device__ uint32_t g_kp  [(size_t)BSZ*NH*SEQ*64];    // k hi/lo
__device__ uint32_t g_vtp [(size_t)BSZ*NH*DH*1024];   // V^T pairs, rows=(bh,d)
__device__ uint32_t g_ctxp[(size_t)8192*512];         // ctx pairs
__device__ float  g_p  [(size_t)BSZ*NH*SEQ*SEQ];      // unnormalized exp(s)
__device__ float  g_rl [(size_t)BSZ*NH*SEQ];          // 1/Z per row

// ---------------------------------------------------------------------------
// Helpers
// ---------------------------------------------------------------------------
__device__ __forceinline__ uint32_t pack16(float a, float b) {
    __half2 h = __floats2half2_rn(a, b);
    return *reinterpret_cast<uint32_t*>(&h);
}

__device__ __forceinline__ void mma16(float c[4], const uint32_t a[4], const uint32_t b[2]) {
    asm volatile(
        "mma.sync.aligned.m16n8k16.row.col.f32.f16.f16.f32 "
        "{%0,%1,%2,%3}, {%4,%5,%6,%7}, {%8,%9}, {%0,%1,%2,%3};"
        : "+f"(c[0]), "+f"(c[1]), "+f"(c[2]), "+f"(c[3])
        : "r"(a[0]), "r"(a[1]), "r"(a[2]), "r"(a[3]), "r"(b[0]), "r"(b[1]));
}

__device__ __forceinline__ void cpasync16(void* dst_smem, const void* src) {
    uint32_t d = (uint32_t)__cvta_generic_to_shared(dst_smem);
    asm volatile("cp.async.ca.shared.global [%0], [%1], 16;" :: "r"(d), "l"(src));
}

// hi/lo f16 split of (v0,v1), each packed with its neighbor
__device__ __forceinline__ void split_pair(float v0, float v1, uint32_t& hi, uint32_t& lo) {
    __half h0 = __float2half_rn(v0), h1 = __float2half_rn(v1);
    __half2 hh = __halves2half2(h0, h1);
    hi = *reinterpret_cast<uint32_t*>(&hh);
    lo = pack16(v0 - __half2float(h0), v1 - __half2float(h1));
}

// ---------------------------------------------------------------------------
// Fused split kernel (one launch)
// ---------------------------------------------------------------------------
__global__ void __launch_bounds__(256)
split_all_kernel(const float* __restrict__ X,
                 const float* __restrict__ Wq, const float* __restrict__ Wk,
                 const float* __restrict__ Wv, const float* __restrict__ Wo,
                 uint32_t* __restrict__ dx,
                 uint32_t* __restrict__ dq, uint32_t* __restrict__ dk,
                 uint32_t* __restrict__ dv, uint32_t* __restrict__ dwo)
{
    const int bid = blockIdx.x;
    if (bid < 16384) {
        const int i = (bid << 8) + threadIdx.x;
        const int r = i >> 9, pe = i & 511;
        float x0 = X[(size_t)r*1024 + pe*2];
        float x1 = X[(size_t)r*1024 + pe*2 + 1];
        uint32_t hi, lo;
        split_pair(x0, x1, hi, lo);
        size_t idx = (size_t)r*1024 + (pe>>3)*16 + (pe&3)*4 + ((pe>>2)&1);
        dx[idx] = hi; dx[idx+2] = lo;
        return;
    }
    const int which = (bid - 16384) >> 11;
    const int i = (((bid - 16384) & 2047) << 8) + threadIdx.x;
    const int r = i >> 9, pe = i & 511;
    if (which < 3) {
        const float* src = (which == 0) ? Wq : (which == 1) ? Wk : Wv;
        uint32_t*    dst = (which == 0) ? dq : (which == 1) ? dk : dv;
        float x0 = src[(size_t)r*1024 + pe*2];
        float x1 = src[(size_t)r*1024 + pe*2 + 1];
        uint32_t hi, lo;
        split_pair(x0, x1, hi, lo);
        size_t idx = (size_t)r*1024 + (pe>>3)*16 + (pe&3)*4 + ((pe>>2)&1);
        dst[idx] = hi; dst[idx+2] = lo;
    } else {
        float x0 = Wo[(size_t)r*1024 + pe*2];
        float x1 = Wo[(size_t)r*1024 + pe*2 + 1];
        size_t idx = (size_t)r*512 + (pe>>3)*8 + (pe&3)*2 + ((pe>>2)&1);
        dwo[idx] = pack16(x0, x1);
    }
}

// ---------------------------------------------------------------------------
// Fused QKV projection GEMM: grid (8, 64, 3).
//  z=0 (Q), z=1 (K): 3-term f16 (hh, hl, lh) — argmax-critical.
//  z=2 (V): single-term.
// ---------------------------------------------------------------------------
#define GP 48

__global__ void __launch_bounds__(256, 2)
gemm_qkv(const uint32_t* __restrict__ Xg,
         const uint32_t* __restrict__ Wqg, const uint32_t* __restrict__ Wkg,
         const uint32_t* __restrict__ Wvg,
         const float* __restrict__ bqg, const float* __restrict__ bkg,
         const float* __restrict__ bvg,
         uint32_t* __restrict__ Oq, uint32_t* __restrict__ Ok,
         uint32_t* __restrict__ Ov)
{
    extern __shared__ uint32_t su[];
    uint32_t* AsB[2] = { su,            su + 2*128*GP };
    uint32_t* BsB[2] = { su + 128*GP,   su + 3*128*GP };

    const int z = blockIdx.z;
    const uint32_t* Bg  = (z == 0) ? Wqg : (z == 1) ? Wkg : Wvg;
    const float*   bias = (z == 0) ? bqg : (z == 1) ? bkg : bvg;
    uint32_t*       Out = (z == 0) ? Oq  : (z == 1) ? Ok  : Ov;
    const float   scale = (z == 0) ? 0.125f : 1.0f;

    const int bm0 = blockIdx.y*128, bn0 = blockIdx.x*128;
    const int tid = threadIdx.x, lane = tid&31, warp = tid>>5;
    const int g = lane>>2, t = lane&3;
    const int wm0 = (warp>>2)*64, wn0 = (warp&3)*32;

    float acc[4][4][4];
    #pragma unroll
    for (int i = 0; i < 4; i++)
        #pragma unroll
        for (int j = 0; j < 4; j++)
            #pragma unroll
            for (int r = 0; r < 4; r++) acc[i][j][r] = 0.f;

    auto load_stage = [&](int kt, int s) {
        #pragma unroll 4
        for (int i = tid; i < 1024; i += 256) {
            int row = i>>3, c4 = (i&7)*4;
            cpasync16(&AsB[s][row*GP + c4], &Xg[(size_t)(bm0+row)*1024 + kt*32 + c4]);
        }
        #pragma unroll 4
        for (int i = tid; i < 1024; i += 256) {
            int row = i>>3, c4 = (i&7)*4;
            cpasync16(&BsB[s][row*GP + c4], &Bg[(size_t)(bn0+row)*1024 + kt*32 + c4]);
        }
        asm volatile("cp.async.commit_group;");
    };

    load_stage(0, 0);
    for (int kt = 0; kt < 32; kt++) {
        const int s = kt & 1;
        if (kt + 1 < 32) {
            load_stage(kt+1, s^1);
            asm volatile("cp.async.wait_group 1;");
        } else {
            asm volatile("cp.async.wait_group 0;");
        }
        __syncthreads();

        const uint32_t* As = AsB[s];
        const uint32_t* Bs = BsB[s];

        #pragma unroll
        for (int ks = 0; ks < 2; ks++) {
            uint32_t ah[4][4], al[4][4], bh[4][2], bl[4][2];
            #pragma unroll
            for (int i = 0; i < 4; i++) {
                uint4 a0 = *(const uint4*)&As[(wm0+i*16+g)  *GP + ks*16 + t*4];
                uint4 a1 = *(const uint4*)&As[(wm0+i*16+8+g)*GP + ks*16 + t*4];
                ah[i][0]=a0.x; ah[i][1]=a1.x; ah[i][2]=a0.y; ah[i][3]=a1.y;
                al[i][0]=a0.z; al[i][1]=a1.z; al[i][2]=a0.w; al[i][3]=a1.w;
            }
            #pragma unroll
            for (int j = 0; j < 4; j++) {
                uint4 bb = *(const uint4*)&Bs[(wn0+j*8+g)*GP + ks*16 + t*4];
                bh[j][0]=bb.x; bh[j][1]=bb.y;
                bl[j][0]=bb.z; bl[j][1]=bb.w;
            }
            #pragma unroll
            for (int i = 0; i < 4; i++)
                #pragma unroll
                for (int j = 0; j < 4; j++)
                    mma16(acc[i][j], ah[i], bh[j]);
            if (z < 2) {
                #pragma unroll
                for (int i = 0; i < 4; i++)
                    #pragma unroll
                    for (int j = 0; j < 4; j++)
                        mma16(acc[i][j], ah[i], bl[j]);
                #pragma unroll
                for (int i = 0; i < 4; i++)
                    #pragma unroll
                    for (int j = 0; j < 4; j++)
                        mma16(acc[i][j], al[i], bh[j]);
            }
        }
        __syncthreads();
    }

    // Epilogue
    #pragma unroll
    for (int i = 0; i < 4; i++) {
        #pragma unroll
        for (int j = 0; j < 4; j++) {
            const int m0 = bm0 + wm0 + i*16 + g;
            const int n0 = bn0 + wn0 + j*8 + 2*t;
            float v0 = (acc[i][j][0] + bias[n0])   * scale;
            float v1 = (acc[i][j][1] + bias[n0+1]) * scale;
            float v2 = (acc[i][j][2] + bias[n0])   * scale;
            float v3 = (acc[i][j][3] + bias[n0+1]) * scale;
            if (z < 2) {
                const int b = m0 >> 11, h = n0 >> 6;
                const int d0 = n0 & 63, pe = d0 >> 1;
                const size_t off = (pe>>3)*16 + (pe&3)*4 + ((pe>>2)&1);
                {
                    int sidx = m0 & (SEQ-1);
                    size_t base = (((size_t)(b*NH + h))*SEQ + sidx)*64 + off;
                    uint32_t hi, lo; split_pair(v0, v1, hi, lo);
                    Out[base] = hi; Out[base+2] = lo;
                }
                {
                    int sidx = (m0+8) & (SEQ-1);
                    size_t base = (((size_t)(b*NH + h))*SEQ + sidx)*64 + off;
                    uint32_t hi, lo; split_pair(v2, v3, hi, lo);
                    Out[base] = hi; Out[base+2] = lo;
                }
            } else {
                float p0 = __shfl_down_sync(0xffffffffu, v0, 4);
                float p1 = __shfl_down_sync(0xffffffffu, v1, 4);
                float p2 = __shfl_down_sync(0xffffffffu, v2, 4);
                float p3 = __shfl_down_sync(0xffffffffu, v3, 4);
                if (!(g & 1)) {
                    const int b = m0 >> 11, h = n0 >> 6;
                    const int d0 = n0 & 63;
                    const int sidx = m0 & (SEQ-1);
                    const size_t r0 = ((size_t)(b*NH + h))*64 + d0;
                    int pe = sidx >> 1;
                    size_t o = (pe>>3)*8 + (pe&3)*2 + ((pe>>2)&1);
                    Out[ r0   *1024 + o] = pack16(v0, p0);
                    Out[(r0+1)*1024 + o] = pack16(v1, p1);
                    int pe8 = (sidx+8) >> 1;
                    size_t o8 = (pe8>>3)*8 + (pe8&3)*2 + ((pe8>>2)&1);
                    Out[ r0   *1024 + o8] = pack16(v2, p2);
                    Out[(r0+1)*1024 + o8] = pack16(v3, p3);
                }
            }
        }
    }
}

// ---------------------------------------------------------------------------
// Flash attention (f16): per (b,h,q-tile 128); 64-key tiles; 256 threads.
// 3x-f16 scores, 1x-f16 PV, fixed-reference softmax. 3-stage cp.async ring.
// ---------------------------------------------------------------------------
#define KP2 80
#define VP2 40
#define FSTG (64*KP2 + 64*VP2 + 64)

__global__ void __launch_bounds__(256)
flash_kernel(const uint32_t* __restrict__ Qp, const uint32_t* __restrict__ Kp,
             const uint32_t* __restrict__ Vtp, const int* __restrict__ mask,
             uint32_t* __restrict__ ctxp, float* __restrict__ P,
             float* __restrict__ grl)
{
    extern __shared__ uint32_t su[];

    const int bh = blockIdx.y;
    const int b  = bh >> 4, h = bh & 15;
    const int q0 = blockIdx.x * 128;
    const int tid = threadIdx.x, lane = tid & 31, warp = tid >> 5;
    const int g = lane >> 2, t = lane & 3;
    const int wr = warp * 16;

    auto ldKV = [&](int kt, int s) {
        uint32_t* st = su + s * FSTG;
        const size_t krow = (size_t)bh*SEQ + kt*64;
        #pragma unroll 4
        for (int i = tid; i < 1024; i += 256) {
            int r = i>>4, c4 = (i&15)*4;
            cpasync16(&st[r*KP2 + c4], &Kp[(krow + r)*64 + c4]);
        }
        const size_t vrow = (size_t)bh*DH;
        #pragma unroll 2
        for (int i = tid; i < 512; i += 256) {
            int r = i>>3, c4 = (i&7)*4;
            cpasync16(&st[64*KP2 + r*VP2 + c4], &Vtp[(vrow + r)*1024 + kt*32 + c4]);
        }
        if (tid < 16)
            cpasync16(&st[64*KP2 + 64*VP2 + tid*4],
                      mask + (size_t)b*SEQ + kt*64 + tid*4);
        asm volatile("cp.async.commit_group;");
    };

    ldKV(0, 0);
    ldKV(1, 1);
    ldKV(2, 2);

    uint32_t qh[4][4], ql[4][4];
    {
        const uint32_t* q0p = Qp + ((size_t)bh*SEQ + q0 + wr + g)*64;
        const uint32_t* q1p = q0p + 8*64;
        #pragma unroll
        for (int kc = 0; kc < 4; kc++) {
            uint4 a0 = *(const uint4*)(q0p + kc*16 + t*4);
            uint4 a1 = *(const uint4*)(q1p + kc*16 + t*4);
            qh[kc][0]=a0.x; qh[kc][1]=a1.x; qh[kc][2]=a0.y; qh[kc][3]=a1.y;
            ql[kc][0]=a0.z; ql[kc][1]=a1.z; ql[kc][2]=a0.w; ql[kc][3]=a1.w;
        }
    }

    const int row0 = q0 + wr + g, row1 = row0 + 8;
    float* prow0 = P + ((size_t)bh*SEQ + row0)*SEQ;
    float* prow1 = P + ((size_t)bh*SEQ + row1)*SEQ;

    float oacc[8][4];
    #pragma unroll
    for (int dj = 0; dj < 8; dj++)
        #pragma unroll
        for (int r = 0; r < 4; r++) oacc[dj][r] = 0.f;
    float l0 = 0.f, l1 = 0.f;

    int sidx3 = 0;   // kt % 3
    for (int kt = 0; kt < 32; kt++) {
        // stage kt must be complete; outstanding groups = min(32,kt+3)-(kt+1)
        if (kt < 30)      { asm volatile("cp.async.wait_group 2;"); }
        else if (kt == 30){ asm volatile("cp.async.wait_group 1;"); }
        else              { asm volatile("cp.async.wait_group 0;"); }
        __syncthreads();

        const uint32_t* Ks = su + sidx3 * FSTG;
        const uint32_t* Vs = Ks + 64*KP2;
        const int*      Mi = (const int*)(Ks + 64*KP2 + 64*VP2);

        float sacc[8][4];
        #pragma unroll
        for (int j = 0; j < 8; j++)
            #pragma unroll
            for (int r = 0; r < 4; r++) sacc[j][r] = 0.f;

        #pragma unroll
        for (int kc = 0; kc < 4; kc++) {
            uint32_t kh2[8][2], kl2[8][2];
            #pragma unroll
            for (int j = 0; j < 8; j++) {
                uint4 kk = *(const uint4*)&Ks[(j*8+g)*KP2 + kc*16 + t*4];
                kh2[j][0] = kk.x; kh2[j][1] = kk.y;
                kl2[j][0] = kk.z; kl2[j][1] = kk.w;
            }
            #pragma unroll
            for (int j = 0; j < 8; j++)
                mma16(sacc[j], qh[kc], kh2[j]);
            #pragma unroll
            for (int j = 0; j < 8; j++)
                mma16(sacc[j], qh[kc], kl2[j]);
            #pragma unroll
            for (int j = 0; j < 8; j++)
                mma16(sacc[j], ql[kc], kh2[j]);
        }

        #pragma unroll
        for (int j = 0; j < 8; j++) {
            float a0 = (Mi[j*8 + 2*t]     == 0) ? -1e30f : 0.f;
            float a1 = (Mi[j*8 + 2*t + 1] == 0) ? -1e30f : 0.f;
            sacc[j][0] = __expf(sacc[j][0] + a0);
            sacc[j][1] = __expf(sacc[j][1] + a1);
            sacc[j][2] = __expf(sacc[j][2] + a0);
            sacc[j][3] = __expf(sacc[j][3] + a1);
            l0 += sacc[j][0] + sacc[j][1];
            l1 += sacc[j][2] + sacc[j][3];
            const int kcol = kt*64 + j*8 + 2*t;
            __stcs((float2*)&prow0[kcol], make_float2(sacc[j][0], sacc[j][1]));
            __stcs((float2*)&prow1[kcol], make_float2(sacc[j][2], sacc[j][3]));
        }

        #pragma unroll
        for (int jj = 0; jj < 4; jj++) {
            uint32_t pa[4] = {
                pack16(sacc[2*jj  ][0], sacc[2*jj  ][1]),
                pack16(sacc[2*jj  ][2], sacc[2*jj  ][3]),
                pack16(sacc[2*jj+1][0], sacc[2*jj+1][1]),
                pack16(sacc[2*jj+1][2], sacc[2*jj+1][3])
            };
            #pragma unroll
            for (int dj = 0; dj < 8; dj++) {
                uint2 vv = *(const uint2*)&Vs[(dj*8+g)*VP2 + jj*8 + t*2];
                uint32_t vb[2] = { vv.x, vv.y };
                mma16(oacc[dj], pa, vb);
            }
        }

        __syncthreads();
        if (kt + 3 < 32) ldKV(kt + 3, sidx3);
        sidx3 = (sidx3 == 2) ? 0 : sidx3 + 1;
    }

    l0 += __shfl_xor_sync(0xffffffffu, l0, 1);
    l0 += __shfl_xor_sync(0xffffffffu, l0, 2);
    l1 += __shfl_xor_sync(0xffffffffu, l1, 1);
    l1 += __shfl_xor_sync(0xffffffffu, l1, 2);
    const float i0 = 1.f / l0, i1 = 1.f / l1;

    #pragma unroll
    for (int dj = 0; dj < 8; dj++) {
        const int c0 = h*64 + dj*8 + 2*t;
        const int pe = c0 >> 1;
        const size_t off = (pe>>3)*8 + (pe&3)*2 + ((pe>>2)&1);
        ctxp[((size_t)b*SEQ + row0)*512 + off] = pack16(oacc[dj][0]*i0, oacc[dj][1]*i0);
        ctxp[((size_t)b*SEQ + row1)*512 + off] = pack16(oacc[dj][2]*i1, oacc[dj][3]*i1);
    }
    if (t == 0) {
        grl[(size_t)bh*SEQ + row0] = i0;
        grl[(size_t)bh*SEQ + row1] = i1;
    }
}

// ---------------------------------------------------------------------------
// Fused O-projection + head-sum/argmax. 8704 blocks:
//   bid % 17 == 0 -> O-proj tile bid/17; else headsum full row
//   (single pass, 8 floats/thread/head -> 32 loads in flight).
// ---------------------------------------------------------------------------
#define OP 40

__global__ void __launch_bounds__(256, 2)
oproj_headsum_kernel(const uint32_t* __restrict__ Ag, const uint32_t* __restrict__ Bg,
                     const float* __restrict__ bias, float* __restrict__ Out,
                     const float* __restrict__ P, const float* __restrict__ rl,
                     float* __restrict__ outIdx)
{
    const int bid = blockIdx.x;
    const int tid = threadIdx.x;

    if (bid % 17 != 0) {
        const int bq = bid - bid/17 - 1;
        const int b = bq >> 11, q = bq & (SEQ-1);

        __shared__ float srl[NH];
        __shared__ float sv[256];
        __shared__ int   si[256];
        if (tid < NH) srl[tid] = rl[((size_t)(b*NH + tid))*SEQ + q];
        __syncthreads();

        const float* rowp[NH];
        #pragma unroll
        for (int h = 0; h < NH; h++)
            rowp[h] = P + (((size_t)(b*NH + h))*SEQ + q)*SEQ;

        const int k = tid * 8;
        float4 s0 = make_float4(0.f, 0.f, 0.f, 0.f);
        float4 s1 = make_float4(0.f, 0.f, 0.f, 0.f);
        #pragma unroll
        for (int h = 0; h < NH; h++) {
            float4 va = __ldcs((const float4*)(rowp[h] + k));
            float4 vb = __ldcs((const float4*)(rowp[h] + k + 4));
            const float r = srl[h];
            s0.x += va.x * r; s0.y += va.y * r; s0.z += va.z * r; s0.w += va.w * r;
            s1.x += vb.x * r; s1.y += vb.y * r; s1.z += vb.z * r; s1.w += vb.w * r;
        }
        float best = s0.x; int bidx = k;
        if (s0.y > best) { best = s0.y; bidx = k + 1; }
        if (s0.z > best) { best = s0.z; bidx = k + 2; }
        if (s0.w > best) { best = s0.w; bidx = k + 3; }
        if (s1.x > best) { best = s1.x; bidx = k + 4; }
        if (s1.y > best) { best = s1.y; bidx = k + 5; }
        if (s1.z > best) { best = s1.z; bidx = k + 6; }
        if (s1.w > best) { best = s1.w; bidx = k + 7; }

        sv[tid] = best; si[tid] = bidx;
        __syncthreads();
        for (int off = 128; off; off >>= 1) {
            if (tid < off) {
                float v2 = sv[tid + off]; int i2 = si[tid + off];
                if (v2 > sv[tid] || (v2 == sv[tid] && i2 < si[tid])) {
                    sv[tid] = v2; si[tid] = i2;
                }
            }
            __syncthreads();
        }
        if (tid == 0) outIdx[bq] = (float)si[0];
        return;
    }

    extern __shared__ uint32_t su[];
    uint32_t* AsB[2] = { su,          su + 2*128*OP };
    uint32_t* BsB[2] = { su + 128*OP, su + 3*128*OP };

    const int tile = bid / 17;
    const int bm0 = (tile >> 3)*128, bn0 = (tile & 7)*128;
    const int lane = tid&31, warp = tid>>5;
    const int g = lane>>2, t = lane&3;
    const int wm0 = (warp>>2)*64, wn0 = (warp&3)*32;

    float acc[4][4][4];
    #pragma unroll
    for (int i = 0; i < 4; i++)
        #pragma unroll
        for (int j = 0; j < 4; j++)
            #pragma unroll
            for (int r = 0; r < 4; r++) acc[i][j][r] = 0.f;

    auto load_stage = [&](int kt, int s) {
        #pragma unroll 4
        for (int i = tid; i < 1024; i += 256) {
            int row = i>>3, c4 = (i&7)*4;
            cpasync16(&AsB[s][row*OP + c4], &Ag[(size_t)(bm0+row)*512 + kt*32 + c4]);
        }
        #pragma unroll 4
        for (int i = tid; i < 1024; i += 256) {
            int row = i>>3, c4 = (i&7)*4;
            cpasync16(&BsB[s][row*OP + c4], &Bg[(size_t)(bn0+row)*512 + kt*32 + c4]);
        }
        asm volatile("cp.async.commit_group;");
    };

    load_stage(0, 0);
    for (int kt = 0; kt < 16; kt++) {
        const int s = kt & 1;
        if (kt + 1 < 16) {
            load_stage(kt+1, s^1);
            asm volatile("cp.async.wait_group 1;");
        } else {
            asm volatile("cp.async.wait_group 0;");
        }
        __syncthreads();

        const uint32_t* As = AsB[s];
        const uint32_t* Bs = BsB[s];

        #pragma unroll
        for (int ks = 0; ks < 4; ks++) {
            uint32_t ah[4][4], bh[4][2];
            #pragma unroll
            for (int i = 0; i < 4; i++) {
                uint2 a0 = *(const uint2*)&As[(wm0+i*16+g)  *OP + ks*8 + t*2];
                uint2 a1 = *(const uint2*)&As[(wm0+i*16+8+g)*OP + ks*8 + t*2];
                ah[i][0]=a0.x; ah[i][1]=a1.x; ah[i][2]=a0.y; ah[i][3]=a1.y;
            }
            #pragma unroll
            for (int j = 0; j < 4; j++) {
                uint2 bb = *(const uint2*)&Bs[(wn0+j*8+g)*OP + ks*8 + t*2];
                bh[j][0]=bb.x; bh[j][1]=bb.y;
            }
            #pragma unroll
            for (int i = 0; i < 4; i++)
                #pragma unroll
                for (int j = 0; j < 4; j++)
                    mma16(acc[i][j], ah[i], bh[j]);
        }
        __syncthreads();
    }

    #pragma unroll
    for (int i = 0; i < 4; i++) {
        #pragma unroll
        for (int j = 0; j < 4; j++) {
            #pragma unroll
            for (int r = 0; r < 4; r++) {
                const int m = bm0 + wm0 + i*16 + g + (r>>1)*8;
                const int n = bn0 + wn0 + j*8 + 2*t + (r&1);
                Out[(size_t)m*1024 + n] = acc[i][j][r] + bias[n];
            }
        }
    }
}

// ---------------------------------------------------------------------------
// Launch
// ---------------------------------------------------------------------------
extern "C" void kernel_launch(void* const* d_in, const int* in_sizes, int n_in,
                              void* d_out, int out_size)
{
    const float* X    = (const float*)d_in[0];
    const int*   mask = (const int*)  d_in[1];
    const float* Wq   = (const float*)d_in[2];
    const float* bq   = (const float*)d_in[3];
    const float* Wk   = (const float*)d_in[4];
    const float* bk   = (const float*)d_in[5];
    const float* Wv   = (const float*)d_in[6];
    const float* bv   = (const float*)d_in[7];
    const float* Wo   = (const float*)d_in[8];
    const float* bo   = (const float*)d_in[9];
    float* out = (float*)d_out;

    static uint32_t *pxp=nullptr,*pwqp=nullptr,*pwkp=nullptr,*pwvp=nullptr,*pwop=nullptr;
    static uint32_t *pqp=nullptr,*pkp=nullptr,*pvtp=nullptr,*pctxp=nullptr;
    static float *pp=nullptr,*prl=nullptr;
    if (!pxp) {
        cudaGetSymbolAddress((void**)&pxp,  g_xp);
        cudaGetSymbolAddress((void**)&pwqp, g_wqp);
        cudaGetSymbolAddress((void**)&pwkp, g_wkp);
        cudaGetSymbolAddress((void**)&pwvp, g_wvp);
        cudaGetSymbolAddress((void**)&pwop, g_wop);
        cudaGetSymbolAddress((void**)&pqp,  g_qp);
        cudaGetSymbolAddress((void**)&pkp,  g_kp);
        cudaGetSymbolAddress((void**)&pvtp, g_vtp);
        cudaGetSymbolAddress((void**)&pctxp,g_ctxp);
        cudaGetSymbolAddress((void**)&pp,   g_p);
        cudaGetSymbolAddress((void**)&prl,  g_rl);
    }

    constexpr int GSM = 4*128*GP*4;          // 98304
    constexpr int OSM = 4*128*OP*4;          // 81920
    constexpr int FSM = 3*FSTG*4;            // 92928

    static bool attr = false;
    if (!attr) {
        attr = true;
        cudaFuncSetAttribute(gemm_qkv,
                             cudaFuncAttributeMaxDynamicSharedMemorySize, GSM);
        cudaFuncSetAttribute(oproj_headsum_kernel,
                             cudaFuncAttributeMaxDynamicSharedMemorySize, OSM);
        cudaFuncSetAttribute(flash_kernel,
                             cudaFuncAttributeMaxDynamicSharedMemorySize, FSM);
    }

    // --- Pre-split inputs (one launch) ---
    split_all_kernel<<<16384 + 4*2048, 256>>>(X, Wq, Wk, Wv, Wo,
                                              pxp, pwqp, pwkp, pwvp, pwop);

    // --- QKV projections (one launch, 1536 blocks) ---
    {
        dim3 grid(8, 64, 3);
        gemm_qkv<<<grid, 256, GSM>>>(pxp, pwqp, pwkp, pwvp, bq, bk, bv,
                                     pqp, pkp, pvtp);
    }

    // --- Fused attention (ctx + p tiles + 1/Z) ---
    {
        dim3 grid(SEQ/128, BSZ*NH);
        flash_kernel<<<grid, 256, FSM>>>(pqp, pkp, pvtp, mask, pctxp, pp, prl);
    }

    // --- Fused O-projection + head-sum/argmax (overlapped) ---
    oproj_headsum_kernel<<<8704, 256, OSM>>>(pctxp, pwop, bo, out, pp, prl,
                                             out + (size_t)BSZ*SEQ*DIM);
}

// round 17
// speedup vs baseline: 1.0367x; 1.0367x over previous
#include <cuda_runtime.h>
#include <cuda_fp16.h>
#include <math.h>
#include <stdint.h>

#define BSZ 4
#define SEQ 2048
#define DIM 1024
#define NH  16
#define DH  64

// ---------------------------------------------------------------------------
// f16 packed layouts (all u32 = __half2):
//  interleaved (hi/lo split operands), per row of C cols: C/16 chunks x 16 u32
//  pairs (single-f16 operands), per row: C/16 chunks x 8 u32
// p layout: [b, h, q, k]
// ---------------------------------------------------------------------------
__device__ uint32_t g_xp  [(size_t)8192*1024];        // X hi/lo interleaved
__device__ uint32_t g_wqp [(size_t)1024*1024];
__device__ uint32_t g_wkp [(size_t)1024*1024];
__device__ uint32_t g_wvp [(size_t)1024*1024];
__device__ uint32_t g_wop [(size_t)1024*512];         // Wo pairs
__device__ uint32_t g_qp  [(size_t)BSZ*NH*SEQ*64];    // q/8 hi/lo, rows=(bh,s)
__device__ uint32_t g_kp  [(size_t)BSZ*NH*SEQ*64];    // k hi/lo
__device__ uint32_t g_vtp [(size_t)BSZ*NH*DH*1024];   // V^T pairs, rows=(bh,d)
__device__ uint32_t g_ctxp[(size_t)8192*512];         // ctx pairs
__device__ float  g_p  [(size_t)BSZ*NH*SEQ*SEQ];      // unnormalized exp(s)
__device__ float  g_rl [(size_t)BSZ*NH*SEQ];          // 1/Z per row

// ---------------------------------------------------------------------------
// Helpers
// ---------------------------------------------------------------------------
__device__ __forceinline__ uint32_t pack16(float a, float b) {
    __half2 h = __floats2half2_rn(a, b);
    return *reinterpret_cast<uint32_t*>(&h);
}

__device__ __forceinline__ void mma16(float c[4], const uint32_t a[4], const uint32_t b[2]) {
    asm volatile(
        "mma.sync.aligned.m16n8k16.row.col.f32.f16.f16.f32 "
        "{%0,%1,%2,%3}, {%4,%5,%6,%7}, {%8,%9}, {%0,%1,%2,%3};"
        : "+f"(c[0]), "+f"(c[1]), "+f"(c[2]), "+f"(c[3])
        : "r"(a[0]), "r"(a[1]), "r"(a[2]), "r"(a[3]), "r"(b[0]), "r"(b[1]));
}

__device__ __forceinline__ void cpasync16(void* dst_smem, const void* src) {
    uint32_t d = (uint32_t)__cvta_generic_to_shared(dst_smem);
    asm volatile("cp.async.ca.shared.global [%0], [%1], 16;" :: "r"(d), "l"(src));
}

// hi/lo f16 split of (v0,v1), each packed with its neighbor
__device__ __forceinline__ void split_pair(float v0, float v1, uint32_t& hi, uint32_t& lo) {
    __half h0 = __float2half_rn(v0), h1 = __float2half_rn(v1);
    __half2 hh = __halves2half2(h0, h1);
    hi = *reinterpret_cast<uint32_t*>(&hh);
    lo = pack16(v0 - __half2float(h0), v1 - __half2float(h1));
}

// ---------------------------------------------------------------------------
// Fused split kernel (one launch)
// ---------------------------------------------------------------------------
__global__ void __launch_bounds__(256)
split_all_kernel(const float* __restrict__ X,
                 const float* __restrict__ Wq, const float* __restrict__ Wk,
                 const float* __restrict__ Wv, const float* __restrict__ Wo,
                 uint32_t* __restrict__ dx,
                 uint32_t* __restrict__ dq, uint32_t* __restrict__ dk,
                 uint32_t* __restrict__ dv, uint32_t* __restrict__ dwo)
{
    const int bid = blockIdx.x;
    if (bid < 16384) {
        const int i = (bid << 8) + threadIdx.x;
        const int r = i >> 9, pe = i & 511;
        float x0 = X[(size_t)r*1024 + pe*2];
        float x1 = X[(size_t)r*1024 + pe*2 + 1];
        uint32_t hi, lo;
        split_pair(x0, x1, hi, lo);
        size_t idx = (size_t)r*1024 + (pe>>3)*16 + (pe&3)*4 + ((pe>>2)&1);
        dx[idx] = hi; dx[idx+2] = lo;
        return;
    }
    const int which = (bid - 16384) >> 11;
    const int i = (((bid - 16384) & 2047) << 8) + threadIdx.x;
    const int r = i >> 9, pe = i & 511;
    if (which < 3) {
        const float* src = (which == 0) ? Wq : (which == 1) ? Wk : Wv;
        uint32_t*    dst = (which == 0) ? dq : (which == 1) ? dk : dv;
        float x0 = src[(size_t)r*1024 + pe*2];
        float x1 = src[(size_t)r*1024 + pe*2 + 1];
        uint32_t hi, lo;
        split_pair(x0, x1, hi, lo);
        size_t idx = (size_t)r*1024 + (pe>>3)*16 + (pe&3)*4 + ((pe>>2)&1);
        dst[idx] = hi; dst[idx+2] = lo;
    } else {
        float x0 = Wo[(size_t)r*1024 + pe*2];
        float x1 = Wo[(size_t)r*1024 + pe*2 + 1];
        size_t idx = (size_t)r*512 + (pe>>3)*8 + (pe&3)*2 + ((pe>>2)&1);
        dwo[idx] = pack16(x0, x1);
    }
}

// ---------------------------------------------------------------------------
// Fused QKV projection GEMM: grid (8, 64, 3).
//  z=0 (Q), z=1 (K): 3-term f16 (hh, hl, lh) — argmax-critical.
//  z=2 (V): single-term.
// ---------------------------------------------------------------------------
#define GP 48

__global__ void __launch_bounds__(256, 2)
gemm_qkv(const uint32_t* __restrict__ Xg,
         const uint32_t* __restrict__ Wqg, const uint32_t* __restrict__ Wkg,
         const uint32_t* __restrict__ Wvg,
         const float* __restrict__ bqg, const float* __restrict__ bkg,
         const float* __restrict__ bvg,
         uint32_t* __restrict__ Oq, uint32_t* __restrict__ Ok,
         uint32_t* __restrict__ Ov)
{
    extern __shared__ uint32_t su[];
    uint32_t* AsB[2] = { su,            su + 2*128*GP };
    uint32_t* BsB[2] = { su + 128*GP,   su + 3*128*GP };

    const int z = blockIdx.z;
    const uint32_t* Bg  = (z == 0) ? Wqg : (z == 1) ? Wkg : Wvg;
    const float*   bias = (z == 0) ? bqg : (z == 1) ? bkg : bvg;
    uint32_t*       Out = (z == 0) ? Oq  : (z == 1) ? Ok  : Ov;
    const float   scale = (z == 0) ? 0.125f : 1.0f;

    const int bm0 = blockIdx.y*128, bn0 = blockIdx.x*128;
    const int tid = threadIdx.x, lane = tid&31, warp = tid>>5;
    const int g = lane>>2, t = lane&3;
    const int wm0 = (warp>>2)*64, wn0 = (warp&3)*32;

    float acc[4][4][4];
    #pragma unroll
    for (int i = 0; i < 4; i++)
        #pragma unroll
        for (int j = 0; j < 4; j++)
            #pragma unroll
            for (int r = 0; r < 4; r++) acc[i][j][r] = 0.f;

    auto load_stage = [&](int kt, int s) {
        #pragma unroll 4
        for (int i = tid; i < 1024; i += 256) {
            int row = i>>3, c4 = (i&7)*4;
            cpasync16(&AsB[s][row*GP + c4], &Xg[(size_t)(bm0+row)*1024 + kt*32 + c4]);
        }
        #pragma unroll 4
        for (int i = tid; i < 1024; i += 256) {
            int row = i>>3, c4 = (i&7)*4;
            cpasync16(&BsB[s][row*GP + c4], &Bg[(size_t)(bn0+row)*1024 + kt*32 + c4]);
        }
        asm volatile("cp.async.commit_group;");
    };

    load_stage(0, 0);
    for (int kt = 0; kt < 32; kt++) {
        const int s = kt & 1;
        if (kt + 1 < 32) {
            load_stage(kt+1, s^1);
            asm volatile("cp.async.wait_group 1;");
        } else {
            asm volatile("cp.async.wait_group 0;");
        }
        __syncthreads();

        const uint32_t* As = AsB[s];
        const uint32_t* Bs = BsB[s];

        #pragma unroll
        for (int ks = 0; ks < 2; ks++) {
            uint32_t ah[4][4], al[4][4], bh[4][2], bl[4][2];
            #pragma unroll
            for (int i = 0; i < 4; i++) {
                uint4 a0 = *(const uint4*)&As[(wm0+i*16+g)  *GP + ks*16 + t*4];
                uint4 a1 = *(const uint4*)&As[(wm0+i*16+8+g)*GP + ks*16 + t*4];
                ah[i][0]=a0.x; ah[i][1]=a1.x; ah[i][2]=a0.y; ah[i][3]=a1.y;
                al[i][0]=a0.z; al[i][1]=a1.z; al[i][2]=a0.w; al[i][3]=a1.w;
            }
            #pragma unroll
            for (int j = 0; j < 4; j++) {
                uint4 bb = *(const uint4*)&Bs[(wn0+j*8+g)*GP + ks*16 + t*4];
                bh[j][0]=bb.x; bh[j][1]=bb.y;
                bl[j][0]=bb.z; bl[j][1]=bb.w;
            }
            #pragma unroll
            for (int i = 0; i < 4; i++)
                #pragma unroll
                for (int j = 0; j < 4; j++)
                    mma16(acc[i][j], ah[i], bh[j]);
            if (z < 2) {
                #pragma unroll
                for (int i = 0; i < 4; i++)
                    #pragma unroll
                    for (int j = 0; j < 4; j++)
                        mma16(acc[i][j], ah[i], bl[j]);
                #pragma unroll
                for (int i = 0; i < 4; i++)
                    #pragma unroll
                    for (int j = 0; j < 4; j++)
                        mma16(acc[i][j], al[i], bh[j]);
            }
        }
        __syncthreads();
    }

    // Epilogue
    #pragma unroll
    for (int i = 0; i < 4; i++) {
        #pragma unroll
        for (int j = 0; j < 4; j++) {
            const int m0 = bm0 + wm0 + i*16 + g;
            const int n0 = bn0 + wn0 + j*8 + 2*t;
            float v0 = (acc[i][j][0] + bias[n0])   * scale;
            float v1 = (acc[i][j][1] + bias[n0+1]) * scale;
            float v2 = (acc[i][j][2] + bias[n0])   * scale;
            float v3 = (acc[i][j][3] + bias[n0+1]) * scale;
            if (z < 2) {
                const int b = m0 >> 11, h = n0 >> 6;
                const int d0 = n0 & 63, pe = d0 >> 1;
                const size_t off = (pe>>3)*16 + (pe&3)*4 + ((pe>>2)&1);
                {
                    int sidx = m0 & (SEQ-1);
                    size_t base = (((size_t)(b*NH + h))*SEQ + sidx)*64 + off;
                    uint32_t hi, lo; split_pair(v0, v1, hi, lo);
                    Out[base] = hi; Out[base+2] = lo;
                }
                {
                    int sidx = (m0+8) & (SEQ-1);
                    size_t base = (((size_t)(b*NH + h))*SEQ + sidx)*64 + off;
                    uint32_t hi, lo; split_pair(v2, v3, hi, lo);
                    Out[base] = hi; Out[base+2] = lo;
                }
            } else {
                float p0 = __shfl_down_sync(0xffffffffu, v0, 4);
                float p1 = __shfl_down_sync(0xffffffffu, v1, 4);
                float p2 = __shfl_down_sync(0xffffffffu, v2, 4);
                float p3 = __shfl_down_sync(0xffffffffu, v3, 4);
                if (!(g & 1)) {
                    const int b = m0 >> 11, h = n0 >> 6;
                    const int d0 = n0 & 63;
                    const int sidx = m0 & (SEQ-1);
                    const size_t r0 = ((size_t)(b*NH + h))*64 + d0;
                    int pe = sidx >> 1;
                    size_t o = (pe>>3)*8 + (pe&3)*2 + ((pe>>2)&1);
                    Out[ r0   *1024 + o] = pack16(v0, p0);
                    Out[(r0+1)*1024 + o] = pack16(v1, p1);
                    int pe8 = (sidx+8) >> 1;
                    size_t o8 = (pe8>>3)*8 + (pe8&3)*2 + ((pe8>>2)&1);
                    Out[ r0   *1024 + o8] = pack16(v2, p2);
                    Out[(r0+1)*1024 + o8] = pack16(v3, p3);
                }
            }
        }
    }
}

// ---------------------------------------------------------------------------
// Flash attention (f16): per (b,h,q-tile 128); 64-key tiles; 256 threads.
// 3x-f16 scores, 1x-f16 PV, fixed-reference softmax. 2-stage ring (R15).
// ---------------------------------------------------------------------------
#define KP2 80
#define VP2 40
#define FSTG (64*KP2 + 64*VP2 + 64)

__global__ void __launch_bounds__(256)
flash_kernel(const uint32_t* __restrict__ Qp, const uint32_t* __restrict__ Kp,
             const uint32_t* __restrict__ Vtp, const int* __restrict__ mask,
             uint32_t* __restrict__ ctxp, float* __restrict__ P,
             float* __restrict__ grl)
{
    extern __shared__ uint32_t su[];

    const int bh = blockIdx.y;
    const int b  = bh >> 4, h = bh & 15;
    const int q0 = blockIdx.x * 128;
    const int tid = threadIdx.x, lane = tid & 31, warp = tid >> 5;
    const int g = lane >> 2, t = lane & 3;
    const int wr = warp * 16;

    auto ldKV = [&](int kt, int s) {
        uint32_t* st = su + s * FSTG;
        const size_t krow = (size_t)bh*SEQ + kt*64;
        #pragma unroll 4
        for (int i = tid; i < 1024; i += 256) {
            int r = i>>4, c4 = (i&15)*4;
            cpasync16(&st[r*KP2 + c4], &Kp[(krow + r)*64 + c4]);
        }
        const size_t vrow = (size_t)bh*DH;
        #pragma unroll 2
        for (int i = tid; i < 512; i += 256) {
            int r = i>>3, c4 = (i&7)*4;
            cpasync16(&st[64*KP2 + r*VP2 + c4], &Vtp[(vrow + r)*1024 + kt*32 + c4]);
        }
        if (tid < 16)
            cpasync16(&st[64*KP2 + 64*VP2 + tid*4],
                      mask + (size_t)b*SEQ + kt*64 + tid*4);
        asm volatile("cp.async.commit_group;");
    };

    ldKV(0, 0);
    ldKV(1, 1);

    uint32_t qh[4][4], ql[4][4];
    {
        const uint32_t* q0p = Qp + ((size_t)bh*SEQ + q0 + wr + g)*64;
        const uint32_t* q1p = q0p + 8*64;
        #pragma unroll
        for (int kc = 0; kc < 4; kc++) {
            uint4 a0 = *(const uint4*)(q0p + kc*16 + t*4);
            uint4 a1 = *(const uint4*)(q1p + kc*16 + t*4);
            qh[kc][0]=a0.x; qh[kc][1]=a1.x; qh[kc][2]=a0.y; qh[kc][3]=a1.y;
            ql[kc][0]=a0.z; ql[kc][1]=a1.z; ql[kc][2]=a0.w; ql[kc][3]=a1.w;
        }
    }

    const int row0 = q0 + wr + g, row1 = row0 + 8;
    float* prow0 = P + ((size_t)bh*SEQ + row0)*SEQ;
    float* prow1 = P + ((size_t)bh*SEQ + row1)*SEQ;

    float oacc[8][4];
    #pragma unroll
    for (int dj = 0; dj < 8; dj++)
        #pragma unroll
        for (int r = 0; r < 4; r++) oacc[dj][r] = 0.f;
    float l0 = 0.f, l1 = 0.f;

    for (int kt = 0; kt < 32; kt++) {
        const int s = kt & 1;
        if (kt < 30) { asm volatile("cp.async.wait_group 1;"); }
        else         { asm volatile("cp.async.wait_group 0;"); }
        __syncthreads();

        const uint32_t* Ks = su + s * FSTG;
        const uint32_t* Vs = Ks + 64*KP2;
        const int*      Mi = (const int*)(Ks + 64*KP2 + 64*VP2);

        float sacc[8][4];
        #pragma unroll
        for (int j = 0; j < 8; j++)
            #pragma unroll
            for (int r = 0; r < 4; r++) sacc[j][r] = 0.f;

        #pragma unroll
        for (int kc = 0; kc < 4; kc++) {
            uint32_t kh2[8][2], kl2[8][2];
            #pragma unroll
            for (int j = 0; j < 8; j++) {
                uint4 kk = *(const uint4*)&Ks[(j*8+g)*KP2 + kc*16 + t*4];
                kh2[j][0] = kk.x; kh2[j][1] = kk.y;
                kl2[j][0] = kk.z; kl2[j][1] = kk.w;
            }
            #pragma unroll
            for (int j = 0; j < 8; j++)
                mma16(sacc[j], qh[kc], kh2[j]);
            #pragma unroll
            for (int j = 0; j < 8; j++)
                mma16(sacc[j], qh[kc], kl2[j]);
            #pragma unroll
            for (int j = 0; j < 8; j++)
                mma16(sacc[j], ql[kc], kh2[j]);
        }

        #pragma unroll
        for (int j = 0; j < 8; j++) {
            float a0 = (Mi[j*8 + 2*t]     == 0) ? -1e30f : 0.f;
            float a1 = (Mi[j*8 + 2*t + 1] == 0) ? -1e30f : 0.f;
            sacc[j][0] = __expf(sacc[j][0] + a0);
            sacc[j][1] = __expf(sacc[j][1] + a1);
            sacc[j][2] = __expf(sacc[j][2] + a0);
            sacc[j][3] = __expf(sacc[j][3] + a1);
            l0 += sacc[j][0] + sacc[j][1];
            l1 += sacc[j][2] + sacc[j][3];
            const int kcol = kt*64 + j*8 + 2*t;
            __stcs((float2*)&prow0[kcol], make_float2(sacc[j][0], sacc[j][1]));
            __stcs((float2*)&prow1[kcol], make_float2(sacc[j][2], sacc[j][3]));
        }

        #pragma unroll
        for (int jj = 0; jj < 4; jj++) {
            uint32_t pa[4] = {
                pack16(sacc[2*jj  ][0], sacc[2*jj  ][1]),
                pack16(sacc[2*jj  ][2], sacc[2*jj  ][3]),
                pack16(sacc[2*jj+1][0], sacc[2*jj+1][1]),
                pack16(sacc[2*jj+1][2], sacc[2*jj+1][3])
            };
            #pragma unroll
            for (int dj = 0; dj < 8; dj++) {
                uint2 vv = *(const uint2*)&Vs[(dj*8+g)*VP2 + jj*8 + t*2];
                uint32_t vb[2] = { vv.x, vv.y };
                mma16(oacc[dj], pa, vb);
            }
        }

        __syncthreads();
        if (kt + 2 < 32) ldKV(kt + 2, s);
    }

    l0 += __shfl_xor_sync(0xffffffffu, l0, 1);
    l0 += __shfl_xor_sync(0xffffffffu, l0, 2);
    l1 += __shfl_xor_sync(0xffffffffu, l1, 1);
    l1 += __shfl_xor_sync(0xffffffffu, l1, 2);
    const float i0 = 1.f / l0, i1 = 1.f / l1;

    #pragma unroll
    for (int dj = 0; dj < 8; dj++) {
        const int c0 = h*64 + dj*8 + 2*t;
        const int pe = c0 >> 1;
        const size_t off = (pe>>3)*8 + (pe&3)*2 + ((pe>>2)&1);
        ctxp[((size_t)b*SEQ + row0)*512 + off] = pack16(oacc[dj][0]*i0, oacc[dj][1]*i0);
        ctxp[((size_t)b*SEQ + row1)*512 + off] = pack16(oacc[dj][2]*i1, oacc[dj][3]*i1);
    }
    if (t == 0) {
        grl[(size_t)bh*SEQ + row0] = i0;
        grl[(size_t)bh*SEQ + row1] = i1;
    }
}

// ---------------------------------------------------------------------------
// Fused O-projection + head-sum/argmax. 8704 blocks:
//   bid % 17 == 0 -> O-proj tile bid/17; else headsum full row
//   (single pass, 8 floats/thread/head -> 32 loads in flight).
// ---------------------------------------------------------------------------
#define OP 40

__global__ void __launch_bounds__(256, 2)
oproj_headsum_kernel(const uint32_t* __restrict__ Ag, const uint32_t* __restrict__ Bg,
                     const float* __restrict__ bias, float* __restrict__ Out,
                     const float* __restrict__ P, const float* __restrict__ rl,
                     float* __restrict__ outIdx)
{
    const int bid = blockIdx.x;
    const int tid = threadIdx.x;

    if (bid % 17 != 0) {
        const int bq = bid - bid/17 - 1;
        const int b = bq >> 11, q = bq & (SEQ-1);

        __shared__ float srl[NH];
        __shared__ float sv[256];
        __shared__ int   si[256];
        if (tid < NH) srl[tid] = rl[((size_t)(b*NH + tid))*SEQ + q];
        __syncthreads();

        const float* rowp[NH];
        #pragma unroll
        for (int h = 0; h < NH; h++)
            rowp[h] = P + (((size_t)(b*NH + h))*SEQ + q)*SEQ;

        const int k = tid * 8;
        float4 s0 = make_float4(0.f, 0.f, 0.f, 0.f);
        float4 s1 = make_float4(0.f, 0.f, 0.f, 0.f);
        #pragma unroll
        for (int h = 0; h < NH; h++) {
            float4 va = __ldcs((const float4*)(rowp[h] + k));
            float4 vb = __ldcs((const float4*)(rowp[h] + k + 4));
            const float r = srl[h];
            s0.x += va.x * r; s0.y += va.y * r; s0.z += va.z * r; s0.w += va.w * r;
            s1.x += vb.x * r; s1.y += vb.y * r; s1.z += vb.z * r; s1.w += vb.w * r;
        }
        float best = s0.x; int bidx = k;
        if (s0.y > best) { best = s0.y; bidx = k + 1; }
        if (s0.z > best) { best = s0.z; bidx = k + 2; }
        if (s0.w > best) { best = s0.w; bidx = k + 3; }
        if (s1.x > best) { best = s1.x; bidx = k + 4; }
        if (s1.y > best) { best = s1.y; bidx = k + 5; }
        if (s1.z > best) { best = s1.z; bidx = k + 6; }
        if (s1.w > best) { best = s1.w; bidx = k + 7; }

        sv[tid] = best; si[tid] = bidx;
        __syncthreads();
        for (int off = 128; off; off >>= 1) {
            if (tid < off) {
                float v2 = sv[tid + off]; int i2 = si[tid + off];
                if (v2 > sv[tid] || (v2 == sv[tid] && i2 < si[tid])) {
                    sv[tid] = v2; si[tid] = i2;
                }
            }
            __syncthreads();
        }
        if (tid == 0) outIdx[bq] = (float)si[0];
        return;
    }

    extern __shared__ uint32_t su[];
    uint32_t* AsB[2] = { su,          su + 2*128*OP };
    uint32_t* BsB[2] = { su + 128*OP, su + 3*128*OP };

    const int tile = bid / 17;
    const int bm0 = (tile >> 3)*128, bn0 = (tile & 7)*128;
    const int lane = tid&31, warp = tid>>5;
    const int g = lane>>2, t = lane&3;
    const int wm0 = (warp>>2)*64, wn0 = (warp&3)*32;

    float acc[4][4][4];
    #pragma unroll
    for (int i = 0; i < 4; i++)
        #pragma unroll
        for (int j = 0; j < 4; j++)
            #pragma unroll
            for (int r = 0; r < 4; r++) acc[i][j][r] = 0.f;

    auto load_stage = [&](int kt, int s) {
        #pragma unroll 4
        for (int i = tid; i < 1024; i += 256) {
            int row = i>>3, c4 = (i&7)*4;
            cpasync16(&AsB[s][row*OP + c4], &Ag[(size_t)(bm0+row)*512 + kt*32 + c4]);
        }
        #pragma unroll 4
        for (int i = tid; i < 1024; i += 256) {
            int row = i>>3, c4 = (i&7)*4;
            cpasync16(&BsB[s][row*OP + c4], &Bg[(size_t)(bn0+row)*512 + kt*32 + c4]);
        }
        asm volatile("cp.async.commit_group;");
    };

    load_stage(0, 0);
    for (int kt = 0; kt < 16; kt++) {
        const int s = kt & 1;
        if (kt + 1 < 16) {
            load_stage(kt+1, s^1);
            asm volatile("cp.async.wait_group 1;");
        } else {
            asm volatile("cp.async.wait_group 0;");
        }
        __syncthreads();

        const uint32_t* As = AsB[s];
        const uint32_t* Bs = BsB[s];

        #pragma unroll
        for (int ks = 0; ks < 4; ks++) {
            uint32_t ah[4][4], bh[4][2];
            #pragma unroll
            for (int i = 0; i < 4; i++) {
                uint2 a0 = *(const uint2*)&As[(wm0+i*16+g)  *OP + ks*8 + t*2];
                uint2 a1 = *(const uint2*)&As[(wm0+i*16+8+g)*OP + ks*8 + t*2];
                ah[i][0]=a0.x; ah[i][1]=a1.x; ah[i][2]=a0.y; ah[i][3]=a1.y;
            }
            #pragma unroll
            for (int j = 0; j < 4; j++) {
                uint2 bb = *(const uint2*)&Bs[(wn0+j*8+g)*OP + ks*8 + t*2];
                bh[j][0]=bb.x; bh[j][1]=bb.y;
            }
            #pragma unroll
            for (int i = 0; i < 4; i++)
                #pragma unroll
                for (int j = 0; j < 4; j++)
                    mma16(acc[i][j], ah[i], bh[j]);
        }
        __syncthreads();
    }

    #pragma unroll
    for (int i = 0; i < 4; i++) {
        #pragma unroll
        for (int j = 0; j < 4; j++) {
            #pragma unroll
            for (int r = 0; r < 4; r++) {
                const int m = bm0 + wm0 + i*16 + g + (r>>1)*8;
                const int n = bn0 + wn0 + j*8 + 2*t + (r&1);
                Out[(size_t)m*1024 + n] = acc[i][j][r] + bias[n];
            }
        }
    }
}

// ---------------------------------------------------------------------------
// Launch
// ---------------------------------------------------------------------------
extern "C" void kernel_launch(void* const* d_in, const int* in_sizes, int n_in,
                              void* d_out, int out_size)
{
    const float* X    = (const float*)d_in[0];
    const int*   mask = (const int*)  d_in[1];
    const float* Wq   = (const float*)d_in[2];
    const float* bq   = (const float*)d_in[3];
    const float* Wk   = (const float*)d_in[4];
    const float* bk   = (const float*)d_in[5];
    const float* Wv   = (const float*)d_in[6];
    const float* bv   = (const float*)d_in[7];
    const float* Wo   = (const float*)d_in[8];
    const float* bo   = (const float*)d_in[9];
    float* out = (float*)d_out;

    static uint32_t *pxp=nullptr,*pwqp=nullptr,*pwkp=nullptr,*pwvp=nullptr,*pwop=nullptr;
    static uint32_t *pqp=nullptr,*pkp=nullptr,*pvtp=nullptr,*pctxp=nullptr;
    static float *pp=nullptr,*prl=nullptr;
    if (!pxp) {
        cudaGetSymbolAddress((void**)&pxp,  g_xp);
        cudaGetSymbolAddress((void**)&pwqp, g_wqp);
        cudaGetSymbolAddress((void**)&pwkp, g_wkp);
        cudaGetSymbolAddress((void**)&pwvp, g_wvp);
        cudaGetSymbolAddress((void**)&pwop, g_wop);
        cudaGetSymbolAddress((void**)&pqp,  g_qp);
        cudaGetSymbolAddress((void**)&pkp,  g_kp);
        cudaGetSymbolAddress((void**)&pvtp, g_vtp);
        cudaGetSymbolAddress((void**)&pctxp,g_ctxp);
        cudaGetSymbolAddress((void**)&pp,   g_p);
        cudaGetSymbolAddress((void**)&prl,  g_rl);
    }

    constexpr int GSM = 4*128*GP*4;          // 98304
    constexpr int OSM = 4*128*OP*4;          // 81920
    constexpr int FSM = 2*FSTG*4;            // 61952

    static bool attr = false;
    if (!attr) {
        attr = true;
        cudaFuncSetAttribute(gemm_qkv,
                             cudaFuncAttributeMaxDynamicSharedMemorySize, GSM);
        cudaFuncSetAttribute(oproj_headsum_kernel,
                             cudaFuncAttributeMaxDynamicSharedMemorySize, OSM);
        cudaFuncSetAttribute(flash_kernel,
                             cudaFuncAttributeMaxDynamicSharedMemorySize, FSM);
    }

    // --- Pre-split inputs (one launch) ---
    split_all_kernel<<<16384 + 4*2048, 256>>>(X, Wq, Wk, Wv, Wo,
                                              pxp, pwqp, pwkp, pwvp, pwop);

    // --- QKV projections (one launch, 1536 blocks) ---
    {
        dim3 grid(8, 64, 3);
        gemm_qkv<<<grid, 256, GSM>>>(pxp, pwqp, pwkp, pwvp, bq, bk, bv,
                                     pqp, pkp, pvtp);
    }

    // --- Fused attention (ctx + p tiles + 1/Z) ---
    {
        dim3 grid(SEQ/128, BSZ*NH);
        flash_kernel<<<grid, 256, FSM>>>(pqp, pkp, pvtp, mask, pctxp, pp, prl);
    }

    // --- Fused O-projection + head-sum/argmax (overlapped) ---
    oproj_headsum_kernel<<<8704, 256, OSM>>>(pctxp, pwop, bo, out, pp, prl,
                                             out + (size_t)BSZ*SEQ*DIM);
}